// round 7
// baseline (speedup 1.0000x reference)
#include <cuda_runtime.h>
#include <math.h>

// Problem constants (B, C, H, W) = (2048, 1, 128, 128)
#define NB       2048
#define IMG_PIX  16384     // 128*128
#define CROP_PIX 4096      // 64*64

// Output layout: concatenation of (target, target_cut, target_scene, target_raw)
#define OFF_TARGET 0
#define OFF_CUT    (2048u * 4096u)
#define OFF_SCENE  (2u * 2048u * 4096u)
#define OFF_RAW    (OFF_SCENE + 2048u * 16384u)

// 256-bit global load/store (sm_100+ / PTX .v8.f32), streaming policy.
__device__ __forceinline__ void ldg256_cs(float* r, const float* p)
{
    asm volatile("ld.global.cs.v8.f32 {%0,%1,%2,%3,%4,%5,%6,%7}, [%8];"
                 : "=f"(r[0]), "=f"(r[1]), "=f"(r[2]), "=f"(r[3]),
                   "=f"(r[4]), "=f"(r[5]), "=f"(r[6]), "=f"(r[7])
                 : "l"(p));
}

__device__ __forceinline__ void stg256_cs(float* p, const float* r)
{
    asm volatile("st.global.cs.v8.f32 [%0], {%1,%2,%3,%4,%5,%6,%7,%8};"
                 :: "l"(p),
                    "f"(r[0]), "f"(r[1]), "f"(r[2]), "f"(r[3]),
                    "f"(r[4]), "f"(r[5]), "f"(r[6]), "f"(r[7])
                 : "memory");
}

__global__ __launch_bounds__(256)
void kd_fused_kernel(const float* __restrict__ image,
                     const float* __restrict__ azimuth,
                     const float* __restrict__ alpha,
                     float* __restrict__ out)
{
    const int b = blockIdx.x;

    const float* img   = image + (size_t)b * IMG_PIX;
    float* targ  = out + OFF_TARGET + (size_t)b * CROP_PIX;
    float* cut   = out + OFF_CUT    + (size_t)b * CROP_PIX;
    float* scene = out + OFF_SCENE  + (size_t)b * IMG_PIX;
    float* raw   = out + OFF_RAW    + (size_t)b * IMG_PIX;

    // Box bounds, replicating reference float32 arithmetic (round = half-to-even).
    float a0 = alpha[0], a1 = alpha[1], a2 = alpha[2], a3 = alpha[3];
    float xu = nearbyintf(__fadd_rn(64.0f, __fmul_rn(__fmul_rn(a0, 70.0f), 0.5f)));
    float xd = nearbyintf(__fsub_rn(64.0f, __fmul_rn(__fmul_rn(a1, 70.0f), 0.5f)));
    float yu = nearbyintf(__fadd_rn(64.0f, __fmul_rn(__fmul_rn(a2, 70.0f), 0.5f)));
    float yd = nearbyintf(__fsub_rn(64.0f, __fmul_rn(__fmul_rn(a3, 70.0f), 0.5f)));

    // masks[b] = rotate(box, -azimuth[b]); a = deg2rad(-az)
    const float ang = __fmul_rn(-azimuth[b], 0.017453292519943295f);
    float sn, cs;
    sincosf(ang, &sn, &cs);
    const float nsn = -sn;

    // Each thread handles 8 consecutive floats (one 256-bit vector).
    // 256 threads * 8 = 2048 floats per pass; 16384/2048 = 8 passes.
    const int lane_col = (threadIdx.x & 15) << 3;   // col0: 0,8,...,120
    const int lane_row = threadIdx.x >> 4;          // 0..15

    #pragma unroll 2
    for (int j = 0; j < 8; j++) {
        const int r  = j * 16 + lane_row;           // row 0..127
        const int g  = (r << 7) + lane_col;         // float index in image

        float v[8];
        ldg256_cs(v, img + g);

        // Mask evaluation for 8 pixels of row r.
        const float Y  = (float)r - 63.5f;
        const float ty = __fmul_rn(sn, Y);   // sin*Y  (xin term)
        const float cy = __fmul_rn(cs, Y);   // cos*Y  (yin term)

        float tg[8], sc[8];
        #pragma unroll
        for (int k = 0; k < 8; k++) {
            const float X   = (float)(lane_col + k) - 63.5f;
            // xin = cos*X + sin*Y ; yin = (-sin)*X + cos*Y  (no FMA, match ref)
            const float xin = __fadd_rn(__fmul_rn(cs,  X), ty);
            const float yin = __fadd_rn(__fmul_rn(nsn, X), cy);
            const float tcol = __fadd_rn(__fadd_rn(xin, 63.5f), 0.5f);
            const float trow = __fadd_rn(__fadd_rn(yin, 63.5f), 0.5f);
            const bool m = (trow >= xd) & (trow < xu) & (tcol >= yd) & (tcol < yu);
            tg[k] = m ? v[k]  : 0.0f;
            sc[k] = m ? 0.0f  : v[k];
        }

        stg256_cs(raw + g, v);
        stg256_cs(scene + g, sc);

        // Central 64x64 crop [32:96]x[32:96] -> target, target_cut
        if (r >= 32 && r < 96 && lane_col >= 32 && lane_col < 96) {
            const int ci = ((r - 32) << 6) + (lane_col - 32);
            stg256_cs(targ + ci, tg);
            float cu[8];
            #pragma unroll
            for (int k = 0; k < 8; k++)
                cu[k] = fminf(__fmul_rn(v[k], 2.0f), 1.0f);
            stg256_cs(cut + ci, cu);
        }
    }
}

extern "C" void kernel_launch(void* const* d_in, const int* in_sizes, int n_in,
                              void* d_out, int out_size)
{
    const float* image   = (const float*)d_in[0];
    const float* azimuth = (const float*)d_in[1];
    const float* alpha   = (const float*)d_in[2];
    float* out = (float*)d_out;

    kd_fused_kernel<<<NB, 256>>>(image, azimuth, alpha, out);
}